// round 1
// baseline (speedup 1.0000x reference)
#include <cuda_runtime.h>

#define NR      96
#define DIM     768
#define TRIU    4560          // C(96,2)
#define P_CNT   9120          // 2*TRIU
#define Q_CNT   9216          // 96*96
#define THR     0.3f
#define SPLITK  8             // 768 / 8 = 96 per split
#define NEG_SLICES 16         // 9216/16 = 576 negs per slice
#define POS_GROUPS 18         // ceil(9120/512)
#define HINGE_BLOCKS (NEG_SLICES * POS_GROUPS)

// ---------------- device scratch (no allocations allowed) ----------------
__device__ float g_Sn[NR * DIM];
__device__ float g_An[NR * DIM];
__device__ float g_partPos[SPLITK * P_CNT];
__device__ float g_partNeg[SPLITK * Q_CNT];
__device__ float g_pos[P_CNT];
__device__ float g_neg[Q_CNT];
__device__ float g_blockSum[HINGE_BLOCKS];

// ---------------- K1: row L2-normalize (192 blocks x 256) ----------------
__global__ void k_normalize(const float* __restrict__ stereos,
                            const float* __restrict__ astereos) {
    int b = blockIdx.x, t = threadIdx.x;
    const float* src = (b < NR) ? (stereos + b * DIM) : (astereos + (b - NR) * DIM);
    float*       dst = (b < NR) ? (g_Sn   + b * DIM) : (g_An    + (b - NR) * DIM);

    float v0 = src[t], v1 = src[t + 256], v2 = src[t + 512];
    float s = v0 * v0 + v1 * v1 + v2 * v2;

    __shared__ float ws[8];
    #pragma unroll
    for (int o = 16; o; o >>= 1) s += __shfl_down_sync(0xffffffffu, s, o);
    if ((t & 31) == 0) ws[t >> 5] = s;
    __syncthreads();
    if (t < 8) {
        float x = ws[t];
        #pragma unroll
        for (int o = 4; o; o >>= 1) x += __shfl_down_sync(0xffu, x, o);
        if (t == 0) ws[0] = x;
    }
    __syncthreads();
    float inv = 1.0f / fmaxf(sqrtf(ws[0]), 1e-8f);
    dst[t] = v0 * inv; dst[t + 256] = v1 * inv; dst[t + 512] = v2 * inv;
}

// ---------------- K2: grams, 32x32 tiles, 2x2/thread, split-K ------------
__device__ __forceinline__ int triu_idx(int i, int j) {
    // linear index of (i,j), i<j, in the upper triangle of a 96x96 matrix
    return i * (191 - i) / 2 + (j - i - 1);
}

__global__ void k_gram() {
    // 21 tiles: 9 for neg (3x3), 6 for posS (tr<=tc), 6 for posA; x SPLITK splits
    __shared__ float As[32][34];
    __shared__ float Bs[32][34];

    int bx = blockIdx.x;
    int sk = bx / 21;
    int tl = bx % 21;

    int m, tr, tc;
    if (tl < 9) { m = 0; tr = tl / 3; tc = tl % 3; }
    else {
        int q = tl - 9;
        m = 1 + q / 6;
        const int TR6[6] = {0,0,0,1,1,2};
        const int TC6[6] = {0,1,2,1,2,2};
        tr = TR6[q % 6]; tc = TC6[q % 6];
    }
    const float* Ap = (m == 1) ? g_Sn : g_An;   // m0: An, m1: Sn, m2: An
    const float* Bp = (m == 2) ? g_An : g_Sn;   // m0: Sn, m1: Sn, m2: An

    int t  = threadIdx.x;
    int tx = t & 15, ty = t >> 4;

    float acc00 = 0.f, acc01 = 0.f, acc10 = 0.f, acc11 = 0.f;

    for (int ch = 0; ch < 3; ch++) {
        int kb = sk * 96 + ch * 32;
        __syncthreads();
        #pragma unroll
        for (int p = 0; p < 4; p++) {
            int lin = t + p * 256;
            int kk  = lin & 31, row = lin >> 5;
            As[kk][row] = Ap[(tr * 32 + row) * DIM + kb + kk];
            Bs[kk][row] = Bp[(tc * 32 + row) * DIM + kb + kk];
        }
        __syncthreads();
        #pragma unroll
        for (int kk = 0; kk < 32; kk++) {
            float2 a = *(const float2*)&As[kk][2 * ty];
            float2 b = *(const float2*)&Bs[kk][2 * tx];
            acc00 += a.x * b.x; acc01 += a.x * b.y;
            acc10 += a.y * b.x; acc11 += a.y * b.y;
        }
    }

    int r0 = tr * 32 + 2 * ty;
    int c0 = tc * 32 + 2 * tx;
    if (m == 0) {
        float* dst = g_partNeg + sk * Q_CNT;
        dst[r0 * 96 + c0]           = acc00;
        dst[r0 * 96 + c0 + 1]       = acc01;
        dst[(r0 + 1) * 96 + c0]     = acc10;
        dst[(r0 + 1) * 96 + c0 + 1] = acc11;
    } else {
        float* dst = g_partPos + sk * P_CNT + ((m == 2) ? TRIU : 0);
        if (r0     < c0    ) dst[triu_idx(r0,     c0    )] = acc00;
        if (r0     < c0 + 1) dst[triu_idx(r0,     c0 + 1)] = acc01;
        if (r0 + 1 < c0    ) dst[triu_idx(r0 + 1, c0    )] = acc10;
        if (r0 + 1 < c0 + 1) dst[triu_idx(r0 + 1, c0 + 1)] = acc11;
    }
}

// ---------------- K2b: fixed-order split-K reduction ----------------------
__global__ void k_combine() {
    int i = blockIdx.x * 256 + threadIdx.x;
    if (i < P_CNT) {
        float s = 0.f;
        #pragma unroll
        for (int sk = 0; sk < SPLITK; sk++) s += g_partPos[sk * P_CNT + i];
        g_pos[i] = s;
    }
    int j = i - P_CNT;
    if (j >= 0 && j < Q_CNT) {
        float s = 0.f;
        #pragma unroll
        for (int sk = 0; sk < SPLITK; sk++) s += g_partNeg[sk * Q_CNT + j];
        g_neg[j] = s;
    }
}

// ---------------- K3: hinge |x| accumulation (288 blocks x 512) -----------
__global__ void k_hinge() {
    __shared__ float4 s_neg4[144];          // 576 negs per slice
    float* s_neg = (float*)s_neg4;

    int ns = blockIdx.x / POS_GROUPS;       // neg slice 0..15
    int pg = blockIdx.x % POS_GROUPS;       // pos group 0..17
    int t  = threadIdx.x;

    int j0 = ns * 576;
    for (int j = t; j < 576; j += 512) s_neg[j] = g_neg[j0 + j];
    __syncthreads();

    float acc = 0.f;
    int pid = pg * 512 + t;
    if (pid < P_CNT) {
        float c = THR - g_pos[pid];
        float a0 = 0.f, a1 = 0.f, a2 = 0.f, a3 = 0.f;
        #pragma unroll 8
        for (int i = 0; i < 144; i++) {
            float4 v = s_neg4[i];
            a0 += fabsf(v.x + c);
            a1 += fabsf(v.y + c);
            a2 += fabsf(v.z + c);
            a3 += fabsf(v.w + c);
        }
        acc = (a0 + a1) + (a2 + a3);
    }

    // block reduce (512 threads, no atomics)
    __shared__ float wsum[16];
    #pragma unroll
    for (int o = 16; o; o >>= 1) acc += __shfl_down_sync(0xffffffffu, acc, o);
    if ((t & 31) == 0) wsum[t >> 5] = acc;
    __syncthreads();
    if (t < 16) {
        float x = wsum[t];
        #pragma unroll
        for (int o = 8; o; o >>= 1) x += __shfl_down_sync(0xffffu, x, o);
        if (t == 0) g_blockSum[blockIdx.x] = x;
    }
}

// ---------------- K4: deterministic final combine --------------------------
__global__ void k_final(float* __restrict__ out) {
    int t = threadIdx.x;  // 256 threads
    double sp = 0.0, sn = 0.0, sb = 0.0;
    for (int i = t; i < P_CNT; i += 256) sp += (double)g_pos[i];
    for (int i = t; i < Q_CNT; i += 256) sn += (double)g_neg[i];
    for (int i = t; i < HINGE_BLOCKS; i += 256) sb += (double)g_blockSum[i];

    __shared__ double rp[256], rn[256], rb[256];
    rp[t] = sp; rn[t] = sn; rb[t] = sb;
    __syncthreads();
    for (int s = 128; s; s >>= 1) {
        if (t < s) { rp[t] += rp[t + s]; rn[t] += rn[t + s]; rb[t] += rb[t + s]; }
        __syncthreads();
    }
    if (t == 0) {
        const double P = (double)P_CNT, Q = (double)Q_CNT, thr = (double)THR;
        // sum over all pairs of x = n - p + thr (separable, exact)
        double Sx = P * rn[0] + Q * (P * thr - rp[0]);
        // mean(max(0,x)) = (Sx + Sum|x|) / (2 P Q)
        out[0] = (float)(0.5 * (Sx + rb[0]) / (P * Q));
    }
}

// ---------------- launch ---------------------------------------------------
extern "C" void kernel_launch(void* const* d_in, const int* in_sizes, int n_in,
                              void* d_out, int out_size) {
    const float* stereos  = (const float*)d_in[0];
    const float* astereos = (const float*)d_in[1];
    float* out = (float*)d_out;

    k_normalize<<<2 * NR, 256>>>(stereos, astereos);
    k_gram<<<21 * SPLITK, 256>>>();
    k_combine<<<(P_CNT + Q_CNT + 255) / 256, 256>>>();
    k_hinge<<<HINGE_BLOCKS, 512>>>();
    k_final<<<1, 256>>>(out);
}

// round 2
// speedup vs baseline: 1.4082x; 1.4082x over previous
#include <cuda_runtime.h>

#define NR      96
#define DIM     768
#define TRIU    4560
#define P_CNT   9120
#define Q_CNT   9216
#define THR     0.3f
#define SPLITK  4              // K split for gram: 768/4 = 192
#define NEG_SL  8              // 8 neg slices of 1152
#define NEG_PER 1152
#define POS_GR  18             // ceil(9120/512)
#define HB      (NEG_SL * POS_GR)   // 144 blocks = 1 wave

// ---------------- device scratch ----------------
__device__ float g_inv[2 * NR];
__device__ float g_partPos[SPLITK * P_CNT];
__device__ float g_partNeg[SPLITK * Q_CNT];
__device__ float g_blockSum[HB];
__device__ float g_posSum[POS_GR];
__device__ float g_negSum[NEG_SL];
__device__ unsigned g_count = 0;

// ---------------- packed f32x2 helpers ----------------
__device__ __forceinline__ unsigned long long addx2(unsigned long long a,
                                                    unsigned long long b) {
    unsigned long long r;
    asm("add.rn.f32x2 %0, %1, %2;" : "=l"(r) : "l"(a), "l"(b));
    return r;
}
#define ABSMASK 0x7fffffff7fffffffULL

// ---------------- K1: inverse row norms (6 blocks x 1024, warp/row) -------
__global__ void k_norms(const float* __restrict__ stereos,
                        const float* __restrict__ astereos) {
    int w = threadIdx.x >> 5, l = threadIdx.x & 31;
    int row = blockIdx.x * 32 + w;                  // 0..191
    const float* src = (row < NR) ? (stereos + row * DIM)
                                  : (astereos + (row - NR) * DIM);
    float s = 0.f;
    #pragma unroll
    for (int k = 0; k < 24; k++) { float v = src[l + 32 * k]; s += v * v; }
    #pragma unroll
    for (int o = 16; o; o >>= 1) s += __shfl_down_sync(0xffffffffu, s, o);
    if (l == 0) g_inv[row] = 1.0f / fmaxf(sqrtf(s), 1e-8f);
}

// ---------------- K2: grams (split-K=4, 21 tiles -> 84 blocks) ------------
__device__ __forceinline__ int triu_idx(int i, int j) {
    return i * (191 - i) / 2 + (j - i - 1);
}

__global__ void k_gram(const float* __restrict__ stereos,
                       const float* __restrict__ astereos) {
    __shared__ float As[32][34];
    __shared__ float Bs[32][34];

    int bx = blockIdx.x;
    int sk = bx / 21;
    int tl = bx % 21;

    int m, tr, tc;
    if (tl < 9) { m = 0; tr = tl / 3; tc = tl % 3; }
    else {
        int q = tl - 9;
        m = 1 + q / 6;
        const int TR6[6] = {0,0,0,1,1,2};
        const int TC6[6] = {0,1,2,1,2,2};
        tr = TR6[q % 6]; tc = TC6[q % 6];
    }
    // m0: neg = A(astereos) x B(stereos); m1: stereos x stereos; m2: astereos x astereos
    const float* Ap = (m == 1) ? stereos : astereos;
    const float* Bp = (m == 2) ? astereos : stereos;
    int invAoff = (m == 1) ? 0 : NR;
    int invBoff = (m == 2) ? NR : 0;

    int t  = threadIdx.x;
    int tx = t & 15, ty = t >> 4;

    float acc00 = 0.f, acc01 = 0.f, acc10 = 0.f, acc11 = 0.f;

    for (int ch = 0; ch < 6; ch++) {
        int kb = sk * 192 + ch * 32;
        __syncthreads();
        #pragma unroll
        for (int p = 0; p < 4; p++) {
            int lin = t + p * 256;
            int kk  = lin & 31, row = lin >> 5;
            As[kk][row] = Ap[(tr * 32 + row) * DIM + kb + kk] * g_inv[invAoff + tr * 32 + row];
            Bs[kk][row] = Bp[(tc * 32 + row) * DIM + kb + kk] * g_inv[invBoff + tc * 32 + row];
        }
        __syncthreads();
        #pragma unroll
        for (int kk = 0; kk < 32; kk++) {
            float2 a = *(const float2*)&As[kk][2 * ty];
            float2 b = *(const float2*)&Bs[kk][2 * tx];
            acc00 += a.x * b.x; acc01 += a.x * b.y;
            acc10 += a.y * b.x; acc11 += a.y * b.y;
        }
    }

    int r0 = tr * 32 + 2 * ty;
    int c0 = tc * 32 + 2 * tx;
    if (m == 0) {
        float* dst = g_partNeg + sk * Q_CNT;
        dst[r0 * 96 + c0]           = acc00;
        dst[r0 * 96 + c0 + 1]       = acc01;
        dst[(r0 + 1) * 96 + c0]     = acc10;
        dst[(r0 + 1) * 96 + c0 + 1] = acc11;
    } else {
        float* dst = g_partPos + sk * P_CNT + ((m == 2) ? TRIU : 0);
        if (r0     < c0    ) dst[triu_idx(r0,     c0    )] = acc00;
        if (r0     < c0 + 1) dst[triu_idx(r0,     c0 + 1)] = acc01;
        if (r0 + 1 < c0    ) dst[triu_idx(r0 + 1, c0    )] = acc10;
        if (r0 + 1 < c0 + 1) dst[triu_idx(r0 + 1, c0 + 1)] = acc11;
    }
}

// ---------------- block reduce (512 threads), fixed order -----------------
__device__ __forceinline__ float blockReduce512(float v, float* sbuf16) {
    __syncthreads();                         // protect sbuf reuse
    int t = threadIdx.x;
    #pragma unroll
    for (int o = 16; o; o >>= 1) v += __shfl_down_sync(0xffffffffu, v, o);
    if ((t & 31) == 0) sbuf16[t >> 5] = v;
    __syncthreads();
    float r = 0.f;
    if (t < 16) {
        r = sbuf16[t];
        #pragma unroll
        for (int o = 8; o; o >>= 1) r += __shfl_down_sync(0xffffu, r, o);
    }
    return r;   // valid at t == 0
}

// ---------------- K3: hinge (144 blocks x 512) + fused final --------------
__global__ void __launch_bounds__(512) k_hinge(float* __restrict__ out) {
    __shared__ __align__(16) float s_neg[NEG_PER];
    __shared__ float sbuf[16];
    __shared__ bool s_last;

    int bid = blockIdx.x;
    int ns  = bid / POS_GR;       // 0..7
    int pg  = bid % POS_GR;       // 0..17
    int t   = threadIdx.x;

    // combine split-K partials for this neg slice into smem (fixed order)
    int j0 = ns * NEG_PER;
    for (int j = t; j < NEG_PER; j += 512) {
        int gj = j0 + j;
        float s = ((g_partNeg[0 * Q_CNT + gj] + g_partNeg[1 * Q_CNT + gj]) +
                   (g_partNeg[2 * Q_CNT + gj] + g_partNeg[3 * Q_CNT + gj]));
        s_neg[j] = s;
    }

    // combine this thread's pos value
    int pid = pg * 512 + t;
    bool act = (pid < P_CNT);
    float posv = 0.f;
    if (act) {
        posv = ((g_partPos[0 * P_CNT + pid] + g_partPos[1 * P_CNT + pid]) +
                (g_partPos[2 * P_CNT + pid] + g_partPos[3 * P_CNT + pid]));
    }
    __syncthreads();

    // designated blocks record sum(pos) / sum(neg) slices
    if (ns == 0) {
        float r = blockReduce512(act ? posv : 0.f, sbuf);
        if (t == 0) g_posSum[pg] = r;
    }
    if (pg == 0) {
        float v = s_neg[t] + s_neg[t + 512] + ((t < 128) ? s_neg[t + 1024] : 0.f);
        float r = blockReduce512(v, sbuf);
        if (t == 0) g_negSum[ns] = r;
    }

    // main hinge: sum |n - p + thr| over slice, packed f32x2
    float acc = 0.f;
    if (act) {
        float c = THR - posv;
        unsigned cu = __float_as_uint(c);
        unsigned long long c2 = ((unsigned long long)cu << 32) | cu;
        const ulonglong2* sn = reinterpret_cast<const ulonglong2*>(s_neg); // 288 entries
        unsigned long long a0 = 0ull, a1 = 0ull, a2 = 0ull, a3 = 0ull;
        #pragma unroll 8
        for (int i = 0; i < NEG_PER / 8; i++) {            // 144 iters, 8 elems each
            ulonglong2 v0 = sn[2 * i];
            ulonglong2 v1 = sn[2 * i + 1];
            a0 = addx2(a0, addx2(v0.x, c2) & ABSMASK);
            a1 = addx2(a1, addx2(v0.y, c2) & ABSMASK);
            a2 = addx2(a2, addx2(v1.x, c2) & ABSMASK);
            a3 = addx2(a3, addx2(v1.y, c2) & ABSMASK);
        }
        float s01 = (__uint_as_float((unsigned)(a0)) + __uint_as_float((unsigned)(a0 >> 32)))
                  + (__uint_as_float((unsigned)(a1)) + __uint_as_float((unsigned)(a1 >> 32)));
        float s23 = (__uint_as_float((unsigned)(a2)) + __uint_as_float((unsigned)(a2 >> 32)))
                  + (__uint_as_float((unsigned)(a3)) + __uint_as_float((unsigned)(a3 >> 32)));
        acc = s01 + s23;
    }
    float bsum = blockReduce512(acc, sbuf);
    if (t == 0) g_blockSum[bid] = bsum;

    // last-block-done: deterministic final combine
    if (t == 0) {
        __threadfence();
        unsigned old = atomicInc(&g_count, HB - 1);  // wraps to 0 on last
        s_last = (old == HB - 1);
    }
    __syncthreads();
    if (!s_last) return;
    __threadfence();

    float vA = (t < HB)     ? g_blockSum[t] : 0.f;
    float S_abs = blockReduce512(vA, sbuf);
    float vP = (t < POS_GR) ? g_posSum[t]   : 0.f;
    float S_pos = blockReduce512(vP, sbuf);
    float vN = (t < NEG_SL) ? g_negSum[t]   : 0.f;
    float S_neg = blockReduce512(vN, sbuf);

    if (t == 0) {
        const double P = (double)P_CNT, Q = (double)Q_CNT, thr = (double)THR;
        double Sx = P * (double)S_neg - Q * (double)S_pos + P * Q * thr;
        out[0] = (float)(0.5 * (Sx + (double)S_abs) / (P * Q));
    }
}

// ---------------- launch ---------------------------------------------------
extern "C" void kernel_launch(void* const* d_in, const int* in_sizes, int n_in,
                              void* d_out, int out_size) {
    const float* stereos  = (const float*)d_in[0];
    const float* astereos = (const float*)d_in[1];
    float* out = (float*)d_out;

    k_norms<<<6, 1024>>>(stereos, astereos);
    k_gram<<<21 * SPLITK, 256>>>(stereos, astereos);
    k_hinge<<<HB, 512>>>(out);
}